// round 2
// baseline (speedup 1.0000x reference)
#include <cuda_runtime.h>
#include <math.h>

#define NN 100000
#define EE 1600000
#define ET (EE + NN)
#define FEAT 128
#define HC 64
#define NH 4
#define NC 40
#define SLOPE 0.2f
#define BNEPS 1e-5f

// ---------------- scratch (device globals; no allocation allowed) ----------------
__device__ float g_h1[NN * HC];     // layer-1 linear output  [N,64]
__device__ float g_o1[NN * HC];     // layer-1 GAT output (+bias1) [N,64]
__device__ float g_h2[NN * NC];     // layer-2 linear output  [N,40]
__device__ float g_as1[NN * NH];
__device__ float g_ad1[NN * NH];
__device__ float g_as2[NN];
__device__ float g_ad2[NN];
__device__ int   g_rowptr[NN + 1];
__device__ int   g_cursor[NN];
__device__ int   g_cnt[NN];
__device__ int   g_srcs[ET];        // CSR-ordered sources
__device__ int   g_src[ET];         // normalized edge list (incl. self loops)
__device__ int   g_dst[ET];
__device__ int   g_bsum[128];
__device__ int   g_is64;

// ---------------- edge dtype detection + normalization ----------------
__global__ void k_detect(const void* ei) {
    if (threadIdx.x == 0 && blockIdx.x == 0) {
        const long long* p = (const long long*)ei;
        int is64 = 1;
        for (int i = 0; i < 8; i++) {
            long long v = p[i];
            if (v < 0 || v >= NN) { is64 = 0; break; }
        }
        g_is64 = is64;
    }
}

__global__ void k_convert(const void* ei) {
    int e = blockIdx.x * blockDim.x + threadIdx.x;
    if (e >= ET) return;
    int src, dst;
    if (e < EE) {
        if (g_is64) {
            const long long* p = (const long long*)ei;
            src = (int)p[e];
            dst = (int)p[EE + e];
        } else {
            const int* p = (const int*)ei;
            src = p[e];
            dst = p[EE + e];
        }
    } else {
        src = e - EE;
        dst = src;
    }
    g_src[e] = src;
    g_dst[e] = dst;
}

// ---------------- CSR build ----------------
__global__ void k_zero() {
    int i = blockIdx.x * blockDim.x + threadIdx.x;
    if (i < NN) g_cnt[i] = 0;
}

__global__ void k_hist() {
    int e = blockIdx.x * blockDim.x + threadIdx.x;
    if (e >= ET) return;
    atomicAdd(&g_cnt[g_dst[e]], 1);
}

__global__ void k_scan1() {  // blockDim must be 1024
    int i = blockIdx.x * 1024 + threadIdx.x;
    int v = (i < NN) ? g_cnt[i] : 0;
    int x = v;
#pragma unroll
    for (int o = 1; o < 32; o <<= 1) {
        int y = __shfl_up_sync(0xffffffffu, x, o);
        if ((threadIdx.x & 31) >= o) x += y;
    }
    __shared__ int ws[32];
    if ((threadIdx.x & 31) == 31) ws[threadIdx.x >> 5] = x;
    __syncthreads();
    if (threadIdx.x < 32) {
        int w = ws[threadIdx.x];
#pragma unroll
        for (int o = 1; o < 32; o <<= 1) {
            int y = __shfl_up_sync(0xffffffffu, w, o);
            if (threadIdx.x >= o) w += y;
        }
        ws[threadIdx.x] = w;
    }
    __syncthreads();
    int add = (threadIdx.x >= 32) ? ws[(threadIdx.x >> 5) - 1] : 0;
    int incl = x + add;
    if (i < NN) g_rowptr[i] = incl - v;          // local exclusive
    if (threadIdx.x == 1023) g_bsum[blockIdx.x] = incl;  // block total
}

__global__ void k_scan2(int nb) {
    if (blockIdx.x == 0 && threadIdx.x == 0) {
        int run = 0;
        for (int b = 0; b < nb; b++) { int t = g_bsum[b]; g_bsum[b] = run; run += t; }
    }
}

__global__ void k_scan3() {
    int i = blockIdx.x * blockDim.x + threadIdx.x;
    if (i < NN) {
        int r = g_rowptr[i] + g_bsum[i >> 10];
        g_rowptr[i] = r;
        g_cursor[i] = r;
    }
    if (i == 0) g_rowptr[NN] = ET;
}

__global__ void k_scatter() {
    int e = blockIdx.x * blockDim.x + threadIdx.x;
    if (e >= ET) return;
    int pos = atomicAdd(&g_cursor[g_dst[e]], 1);
    g_srcs[pos] = g_src[e];
}

// ---------------- GEMM1: h1 = x @ W1   (x: [N,128], W1: [128,64]) ----------------
// 128x64 block tile, 256 threads, thread tile 8x4, K staged in chunks of 32.
__global__ void k_gemm1(const float* __restrict__ x, const float* __restrict__ W) {
    __shared__ float As[32][129];   // [k][m], padded for conflict-free transpose
    __shared__ float Bs[32][64];    // [k][n]
    int tid = threadIdx.x;
    int tx = tid & 15, ty = tid >> 4;      // tx: n-dir (4 cols), ty: m-dir (8 rows)
    int mBase = blockIdx.x * 128;
    float acc[8][4];
#pragma unroll
    for (int i = 0; i < 8; i++)
#pragma unroll
        for (int j = 0; j < 4; j++) acc[i][j] = 0.f;

    for (int k0 = 0; k0 < FEAT; k0 += 32) {
        for (int idx = tid; idx < 128 * 32; idx += 256) {
            int m = idx >> 5, kk = idx & 31;
            int gm = mBase + m;
            As[kk][m] = (gm < NN) ? x[gm * FEAT + k0 + kk] : 0.f;
        }
        for (int idx = tid; idx < 32 * 64; idx += 256)
            Bs[idx >> 6][idx & 63] = W[(k0 + (idx >> 6)) * HC + (idx & 63)];
        __syncthreads();
#pragma unroll
        for (int kk = 0; kk < 32; kk++) {
            float4 bv = *(const float4*)&Bs[kk][tx * 4];
#pragma unroll
            for (int i = 0; i < 8; i++) {
                float a = As[kk][ty * 8 + i];
                acc[i][0] += a * bv.x;
                acc[i][1] += a * bv.y;
                acc[i][2] += a * bv.z;
                acc[i][3] += a * bv.w;
            }
        }
        __syncthreads();
    }
#pragma unroll
    for (int i = 0; i < 8; i++) {
        int gm = mBase + ty * 8 + i;
        if (gm < NN) {
            float4 v = make_float4(acc[i][0], acc[i][1], acc[i][2], acc[i][3]);
            *(float4*)&g_h1[gm * HC + tx * 4] = v;
        }
    }
}

// ---------------- attention scalars layer 1 (warp per node) ----------------
__global__ void k_attn1(const float* __restrict__ asv, const float* __restrict__ adv) {
    int t = blockIdx.x * blockDim.x + threadIdx.x;
    int node = t >> 5, lane = t & 31;
    if (node >= NN) return;
    float2 h = *(const float2*)&g_h1[node * HC + 2 * lane];
    float ps = h.x * asv[2 * lane] + h.y * asv[2 * lane + 1];
    float pd = h.x * adv[2 * lane] + h.y * adv[2 * lane + 1];
#pragma unroll
    for (int o = 4; o >= 1; o >>= 1) {
        ps += __shfl_xor_sync(0xffffffffu, ps, o);
        pd += __shfl_xor_sync(0xffffffffu, pd, o);
    }
    if ((lane & 7) == 0) {
        g_as1[node * NH + (lane >> 3)] = ps;
        g_ad1[node * NH + (lane >> 3)] = pd;
    }
}

// ---------------- layer-1 softmax aggregation (warp per dst node) ----------------
__global__ void k_agg1(const float* __restrict__ bias) {
    int t = blockIdx.x * blockDim.x + threadIdx.x;
    int node = t >> 5, lane = t & 31;
    if (node >= NN) return;
    int beg = g_rowptr[node], end = g_rowptr[node + 1];
    float4 adv = *(const float4*)&g_ad1[node * NH];

    // pass 1: per-head max over incoming edges (lanes stride edges)
    float m0 = -1e30f, m1 = -1e30f, m2 = -1e30f, m3 = -1e30f;
    for (int i = beg + lane; i < end; i += 32) {
        int s = g_srcs[i];
        float4 av = *(const float4*)&g_as1[s * NH];
        float a0 = av.x + adv.x, a1 = av.y + adv.y, a2 = av.z + adv.z, a3 = av.w + adv.w;
        a0 = fmaxf(a0, SLOPE * a0); a1 = fmaxf(a1, SLOPE * a1);
        a2 = fmaxf(a2, SLOPE * a2); a3 = fmaxf(a3, SLOPE * a3);
        m0 = fmaxf(m0, a0); m1 = fmaxf(m1, a1); m2 = fmaxf(m2, a2); m3 = fmaxf(m3, a3);
    }
#pragma unroll
    for (int o = 16; o >= 1; o >>= 1) {
        m0 = fmaxf(m0, __shfl_xor_sync(0xffffffffu, m0, o));
        m1 = fmaxf(m1, __shfl_xor_sync(0xffffffffu, m1, o));
        m2 = fmaxf(m2, __shfl_xor_sync(0xffffffffu, m2, o));
        m3 = fmaxf(m3, __shfl_xor_sync(0xffffffffu, m3, o));
    }
    int hsel = lane >> 3;  // channels {2*lane, 2*lane+1} belong to head lane/8
    float mh  = (hsel == 0) ? m0 : (hsel == 1) ? m1 : (hsel == 2) ? m2 : m3;
    float adh = (hsel == 0) ? adv.x : (hsel == 1) ? adv.y : (hsel == 2) ? adv.z : adv.w;

    // pass 2: fused exp-weighted accumulation; every lane walks every edge
    float acc0 = 0.f, acc1 = 0.f, sex = 0.f;
    for (int i = beg; i < end; i++) {
        int s = g_srcs[i];
        float a = g_as1[s * NH + hsel] + adh;
        a = fmaxf(a, SLOPE * a);
        float ex = __expf(a - mh);
        float2 hv = *(const float2*)&g_h1[s * HC + 2 * lane];
        acc0 += ex * hv.x;
        acc1 += ex * hv.y;
        sex += ex;
    }
    float inv = 1.0f / sex;
    float2 o;
    o.x = acc0 * inv + bias[2 * lane];
    o.y = acc1 * inv + bias[2 * lane + 1];
    *(float2*)&g_o1[node * HC + 2 * lane] = o;
}

// ---------------- GEMM2: h2 = relu(BN(o1)) @ W2  ([N,64] @ [64,40]) ----------------
__global__ void k_gemm2(const float* __restrict__ W2,
                        const float* __restrict__ gamma, const float* __restrict__ beta,
                        const float* __restrict__ mean, const float* __restrict__ var) {
    __shared__ float As[32][129];
    __shared__ float Bs[32][64];   // only cols 0..39 valid; padded for safe OOB lane reads
    __shared__ float sc[64], sh[64];
    int tid = threadIdx.x;  // 256
    if (tid < 64) {
        float s = gamma[tid] * rsqrtf(var[tid] + BNEPS);
        sc[tid] = s;
        sh[tid] = beta[tid] - mean[tid] * s;
    }
    __syncthreads();
    int tx = tid & 15, ty = tid >> 4;
    int mBase = blockIdx.x * 128;
    float acc[8][4];
#pragma unroll
    for (int i = 0; i < 8; i++)
#pragma unroll
        for (int j = 0; j < 4; j++) acc[i][j] = 0.f;

    for (int k0 = 0; k0 < HC; k0 += 32) {
        for (int idx = tid; idx < 128 * 32; idx += 256) {
            int m = idx >> 5, kk = idx & 31;
            int gm = mBase + m;
            int k = k0 + kk;
            float v = (gm < NN) ? g_o1[gm * HC + k] : 0.f;
            As[kk][m] = fmaxf(v * sc[k] + sh[k], 0.f);
        }
        for (int idx = tid; idx < 32 * 64; idx += 256) {
            int r = idx >> 6, c = idx & 63;
            Bs[r][c] = (c < NC) ? W2[(k0 + r) * NC + c] : 0.f;
        }
        __syncthreads();
#pragma unroll
        for (int kk = 0; kk < 32; kk++) {
            float4 bv = *(const float4*)&Bs[kk][tx * 4];
#pragma unroll
            for (int i = 0; i < 8; i++) {
                float a = As[kk][ty * 8 + i];
                acc[i][0] += a * bv.x;
                acc[i][1] += a * bv.y;
                acc[i][2] += a * bv.z;
                acc[i][3] += a * bv.w;
            }
        }
        __syncthreads();
    }
    if (tx < 10) {
#pragma unroll
        for (int i = 0; i < 8; i++) {
            int gm = mBase + ty * 8 + i;
            if (gm < NN) {
                float4 v = make_float4(acc[i][0], acc[i][1], acc[i][2], acc[i][3]);
                *(float4*)&g_h2[gm * NC + tx * 4] = v;
            }
        }
    }
}

// ---------------- attention scalars layer 2 (warp per node) ----------------
__global__ void k_attn2(const float* __restrict__ asv, const float* __restrict__ adv) {
    int t = blockIdx.x * blockDim.x + threadIdx.x;
    int node = t >> 5, lane = t & 31;
    if (node >= NN) return;
    float v = g_h2[node * NC + lane];
    float ps = v * asv[lane], pd = v * adv[lane];
    if (lane < 8) {
        float w = g_h2[node * NC + 32 + lane];
        ps += w * asv[32 + lane];
        pd += w * adv[32 + lane];
    }
#pragma unroll
    for (int o = 16; o >= 1; o >>= 1) {
        ps += __shfl_xor_sync(0xffffffffu, ps, o);
        pd += __shfl_xor_sync(0xffffffffu, pd, o);
    }
    if (lane == 0) { g_as2[node] = ps; g_ad2[node] = pd; }
}

// ---------------- layer-2 softmax aggregation -> output ----------------
__global__ void k_agg2(const float* __restrict__ bias, float* __restrict__ out) {
    int t = blockIdx.x * blockDim.x + threadIdx.x;
    int node = t >> 5, lane = t & 31;
    if (node >= NN) return;
    int beg = g_rowptr[node], end = g_rowptr[node + 1];
    float ad = g_ad2[node];

    float m = -1e30f;
    for (int i = beg + lane; i < end; i += 32) {
        int s = g_srcs[i];
        float a = g_as2[s] + ad;
        a = fmaxf(a, SLOPE * a);
        m = fmaxf(m, a);
    }
#pragma unroll
    for (int o = 16; o >= 1; o >>= 1)
        m = fmaxf(m, __shfl_xor_sync(0xffffffffu, m, o));

    float acc0 = 0.f, acc1 = 0.f, sex = 0.f;
    for (int i = beg; i < end; i++) {
        int s = g_srcs[i];
        float a = g_as2[s] + ad;
        a = fmaxf(a, SLOPE * a);
        float ex = __expf(a - m);
        sex += ex;
        acc0 += ex * g_h2[s * NC + lane];
        if (lane < 8) acc1 += ex * g_h2[s * NC + 32 + lane];
    }
    float inv = 1.0f / sex;
    out[node * NC + lane] = acc0 * inv + bias[lane];
    if (lane < 8) out[node * NC + 32 + lane] = acc1 * inv + bias[32 + lane];
}

// ---------------- launch ----------------
extern "C" void kernel_launch(void* const* d_in, const int* in_sizes, int n_in,
                              void* d_out, int out_size) {
    const float* x    = (const float*)d_in[0];
    const void*  ei   = d_in[1];
    const float* W1   = (const float*)d_in[2];
    const float* as1  = (const float*)d_in[3];
    const float* ad1  = (const float*)d_in[4];
    const float* b1   = (const float*)d_in[5];
    const float* bngm = (const float*)d_in[6];
    const float* bnbt = (const float*)d_in[7];
    const float* bnmu = (const float*)d_in[8];
    const float* bnvr = (const float*)d_in[9];
    const float* W2   = (const float*)d_in[10];
    const float* as2  = (const float*)d_in[11];
    const float* ad2  = (const float*)d_in[12];
    const float* b2   = (const float*)d_in[13];
    float*       out  = (float*)d_out;

    // edge normalization (dtype-robust) + CSR build
    k_detect<<<1, 32>>>(ei);
    k_convert<<<(ET + 255) / 256, 256>>>(ei);
    k_zero<<<(NN + 255) / 256, 256>>>();
    k_hist<<<(ET + 255) / 256, 256>>>();
    int nb = (NN + 1023) / 1024;
    k_scan1<<<nb, 1024>>>();
    k_scan2<<<1, 32>>>(nb);
    k_scan3<<<(NN + 255) / 256, 256>>>();
    k_scatter<<<(ET + 255) / 256, 256>>>();

    // layer 1
    k_gemm1<<<(NN + 127) / 128, 256>>>(x, W1);
    k_attn1<<<(NN * 32 + 255) / 256, 256>>>(as1, ad1);
    k_agg1<<<(NN * 32 + 255) / 256, 256>>>(b1);

    // layer 2 (BN+ReLU fused into GEMM2 A-tile load)
    k_gemm2<<<(NN + 127) / 128, 256>>>(W2, bngm, bnbt, bnmu, bnvr);
    k_attn2<<<(NN * 32 + 255) / 256, 256>>>(as2, ad2);
    k_agg2<<<(NN * 32 + 255) / 256, 256>>>(b2, out);
}

// round 3
// speedup vs baseline: 1.1539x; 1.1539x over previous
#include <cuda_runtime.h>
#include <math.h>

#define NN 100000
#define EE 1600000
#define ET (EE + NN)
#define FEAT 128
#define HC 64
#define NH 4
#define NC 40
#define SLOPE 0.2f
#define BNEPS 1e-5f

typedef unsigned long long ull;

// ---------------- scratch ----------------
__device__ float g_h1[NN * HC];
__device__ float g_o1[NN * HC];
__device__ float g_h2[NN * NC];
__device__ float g_as1[NN * NH];
__device__ float g_ad1[NN * NH];
__device__ float g_as2[NN];
__device__ float g_ad2[NN];
__device__ int   g_rowptr[NN + 1];
__device__ int   g_cursor[NN];
__device__ int   g_cnt[NN];
__device__ int   g_srcs[ET];
__device__ int   g_src[ET];
__device__ int   g_dst[ET];
__device__ int   g_bsum[128];
__device__ int   g_is64;

// ---------------- f32x2 helpers ----------------
__device__ __forceinline__ ull fma2(ull a, ull b, ull c) {
    ull d;
    asm("fma.rn.f32x2 %0, %1, %2, %3;" : "=l"(d) : "l"(a), "l"(b), "l"(c));
    return d;
}
__device__ __forceinline__ ull splat2(float x) {
    ull r;
    asm("mov.b64 %0, {%1, %1};" : "=l"(r) : "f"(x));
    return r;
}
__device__ __forceinline__ void unpack2(ull v, float& lo, float& hi) {
    asm("mov.b64 {%0, %1}, %2;" : "=f"(lo), "=f"(hi) : "l"(v));
}

// ---------------- init: zero counters + edge dtype probe ----------------
__global__ void k_init(const void* ei) {
    int i = blockIdx.x * blockDim.x + threadIdx.x;
    if (i < NN) g_cnt[i] = 0;
    if (i == 0) {
        const long long* p = (const long long*)ei;
        int is64 = 1;
        for (int j = 0; j < 8; j++) {
            long long v = p[j];
            if (v < 0 || v >= NN) { is64 = 0; break; }
        }
        g_is64 = is64;
    }
}

// ---------------- convert + histogram (fused) ----------------
__global__ void k_convert_hist(const void* ei) {
    int e = blockIdx.x * blockDim.x + threadIdx.x;
    if (e >= ET) return;
    int src, dst;
    if (e < EE) {
        if (g_is64) {
            const long long* p = (const long long*)ei;
            src = (int)p[e];
            dst = (int)p[EE + e];
        } else {
            const int* p = (const int*)ei;
            src = p[e];
            dst = p[EE + e];
        }
    } else {
        src = e - EE;
        dst = src;
    }
    g_src[e] = src;
    g_dst[e] = dst;
    atomicAdd(&g_cnt[dst], 1);
}

// ---------------- scan ----------------
__global__ void k_scan1() {  // blockDim = 1024
    int i = blockIdx.x * 1024 + threadIdx.x;
    int v = (i < NN) ? g_cnt[i] : 0;
    int x = v;
#pragma unroll
    for (int o = 1; o < 32; o <<= 1) {
        int y = __shfl_up_sync(0xffffffffu, x, o);
        if ((threadIdx.x & 31) >= o) x += y;
    }
    __shared__ int ws[32];
    if ((threadIdx.x & 31) == 31) ws[threadIdx.x >> 5] = x;
    __syncthreads();
    if (threadIdx.x < 32) {
        int w = ws[threadIdx.x];
#pragma unroll
        for (int o = 1; o < 32; o <<= 1) {
            int y = __shfl_up_sync(0xffffffffu, w, o);
            if (threadIdx.x >= o) w += y;
        }
        ws[threadIdx.x] = w;
    }
    __syncthreads();
    int add = (threadIdx.x >= 32) ? ws[(threadIdx.x >> 5) - 1] : 0;
    int incl = x + add;
    if (i < NN) g_rowptr[i] = incl - v;
    if (threadIdx.x == 1023) g_bsum[blockIdx.x] = incl;
}

__global__ void k_scan2(int nb) {
    if (threadIdx.x == 0) {
        int run = 0;
        for (int b = 0; b < nb; b++) { int t = g_bsum[b]; g_bsum[b] = run; run += t; }
    }
}

__global__ void k_scan3() {
    int i = blockIdx.x * blockDim.x + threadIdx.x;
    if (i < NN) {
        int r = g_rowptr[i] + g_bsum[i >> 10];
        g_rowptr[i] = r;
        g_cursor[i] = r;
    }
    if (i == 0) g_rowptr[NN] = ET;
}

__global__ void k_scatter() {
    int e = blockIdx.x * blockDim.x + threadIdx.x;
    if (e >= ET) return;
    int pos = atomicAdd(&g_cursor[g_dst[e]], 1);
    g_srcs[pos] = g_src[e];
}

// ---------------- GEMM1: h1 = x @ W1, fused attention scalars (f32x2) ----------------
__global__ void k_gemm1(const float* __restrict__ x, const float* __restrict__ W,
                        const float* __restrict__ attS, const float* __restrict__ attD) {
    __shared__ __align__(16) float As[32][130];   // even stride for 64-bit LDS
    __shared__ __align__(16) float Bs[32][64];
    int tid = threadIdx.x;
    int tx = tid & 15, ty = tid >> 4;
    int mBase = blockIdx.x * 128;

    float as_v[4], ad_v[4];
#pragma unroll
    for (int j = 0; j < 4; j++) {
        as_v[j] = attS[tx * 4 + j];
        ad_v[j] = attD[tx * 4 + j];
    }

    ull acc[4][4];
#pragma unroll
    for (int p = 0; p < 4; p++)
#pragma unroll
        for (int j = 0; j < 4; j++) acc[p][j] = 0ull;

    for (int k0 = 0; k0 < FEAT; k0 += 32) {
        for (int idx = tid; idx < 128 * 32; idx += 256) {
            int m = idx >> 5, kk = idx & 31;
            int gm = mBase + m;
            As[kk][m] = (gm < NN) ? x[gm * FEAT + k0 + kk] : 0.f;
        }
        for (int idx = tid; idx < 32 * 64; idx += 256)
            Bs[idx >> 6][idx & 63] = W[(k0 + (idx >> 6)) * HC + (idx & 63)];
        __syncthreads();
#pragma unroll
        for (int kk = 0; kk < 32; kk++) {
            float4 bv = *(const float4*)&Bs[kk][tx * 4];
            ull b0 = splat2(bv.x), b1 = splat2(bv.y), b2 = splat2(bv.z), b3 = splat2(bv.w);
#pragma unroll
            for (int p = 0; p < 4; p++) {
                ull a = *(const ull*)&As[kk][ty * 8 + 2 * p];
                acc[p][0] = fma2(a, b0, acc[p][0]);
                acc[p][1] = fma2(a, b1, acc[p][1]);
                acc[p][2] = fma2(a, b2, acc[p][2]);
                acc[p][3] = fma2(a, b3, acc[p][3]);
            }
        }
        __syncthreads();
    }

    // epilogue: unpack, store h1, fused per-head attention dots
#pragma unroll
    for (int p = 0; p < 4; p++) {
        float lo[4], hi[4];
#pragma unroll
        for (int j = 0; j < 4; j++) unpack2(acc[p][j], lo[j], hi[j]);
#pragma unroll
        for (int half = 0; half < 2; half++) {
            float* f = half ? hi : lo;
            int r = 2 * p + half;
            int gm = mBase + ty * 8 + r;
            if (gm < NN) {
                *(float4*)&g_h1[gm * HC + tx * 4] = make_float4(f[0], f[1], f[2], f[3]);
                float ps = f[0] * as_v[0] + f[1] * as_v[1] + f[2] * as_v[2] + f[3] * as_v[3];
                float pd = f[0] * ad_v[0] + f[1] * ad_v[1] + f[2] * ad_v[2] + f[3] * ad_v[3];
                ps += __shfl_xor_sync(0xffffffffu, ps, 1);
                pd += __shfl_xor_sync(0xffffffffu, pd, 1);
                ps += __shfl_xor_sync(0xffffffffu, ps, 2);
                pd += __shfl_xor_sync(0xffffffffu, pd, 2);
                if ((tx & 3) == 0) {
                    g_as1[gm * NH + (tx >> 2)] = ps;
                    g_ad1[gm * NH + (tx >> 2)] = pd;
                }
            } else {
                // keep shuffles convergent
                float z = 0.f;
                z += __shfl_xor_sync(0xffffffffu, z, 1);
                z += __shfl_xor_sync(0xffffffffu, z, 1);
                z += __shfl_xor_sync(0xffffffffu, z, 2);
                z += __shfl_xor_sync(0xffffffffu, z, 2);
            }
        }
    }
}

// ---------------- layer-1 softmax aggregation: 2 edges/warp-iter, float4 lanes ----------------
__global__ void k_agg1(const float* __restrict__ bias) {
    int t = blockIdx.x * blockDim.x + threadIdx.x;
    int node = t >> 5, lane = t & 31;
    if (node >= NN) return;
    int beg = g_rowptr[node], end = g_rowptr[node + 1];
    float4 adv = *(const float4*)&g_ad1[node * NH];

    // pass 1: per-head max (lanes stride edges by 32)
    float m0 = -1e30f, m1 = -1e30f, m2 = -1e30f, m3 = -1e30f;
    for (int i = beg + lane; i < end; i += 32) {
        int s = g_srcs[i];
        float4 av = *(const float4*)&g_as1[s * NH];
        float a0 = av.x + adv.x, a1 = av.y + adv.y, a2 = av.z + adv.z, a3 = av.w + adv.w;
        a0 = fmaxf(a0, SLOPE * a0); a1 = fmaxf(a1, SLOPE * a1);
        a2 = fmaxf(a2, SLOPE * a2); a3 = fmaxf(a3, SLOPE * a3);
        m0 = fmaxf(m0, a0); m1 = fmaxf(m1, a1); m2 = fmaxf(m2, a2); m3 = fmaxf(m3, a3);
    }
#pragma unroll
    for (int o = 16; o >= 1; o >>= 1) {
        m0 = fmaxf(m0, __shfl_xor_sync(0xffffffffu, m0, o));
        m1 = fmaxf(m1, __shfl_xor_sync(0xffffffffu, m1, o));
        m2 = fmaxf(m2, __shfl_xor_sync(0xffffffffu, m2, o));
        m3 = fmaxf(m3, __shfl_xor_sync(0xffffffffu, m3, o));
    }

    // pass 2: 16 lanes per edge (float4 channels), 2 edges per iteration
    int half = lane >> 4;        // which edge of the pair
    int l = lane & 15;           // channel group: channels l*4 .. l*4+3
    int hsel = l >> 2;           // head
    float mh  = (hsel == 0) ? m0 : (hsel == 1) ? m1 : (hsel == 2) ? m2 : m3;
    float adh = (hsel == 0) ? adv.x : (hsel == 1) ? adv.y : (hsel == 2) ? adv.z : adv.w;

    float4 acc = make_float4(0.f, 0.f, 0.f, 0.f);
    float sex = 0.f;
    int i = beg + half;
    int s = (i < end) ? g_srcs[i] : 0;
    while (i < end) {
        int inext = i + 2;
        int snext = (inext < end) ? g_srcs[inext] : 0;
        float a = g_as1[s * NH + hsel] + adh;
        a = fmaxf(a, SLOPE * a);
        float ex = __expf(a - mh);
        float4 hv = *(const float4*)&g_h1[s * HC + l * 4];
        acc.x += ex * hv.x; acc.y += ex * hv.y;
        acc.z += ex * hv.z; acc.w += ex * hv.w;
        sex += ex;
        i = inext; s = snext;
    }
    // combine the two halves
    acc.x += __shfl_xor_sync(0xffffffffu, acc.x, 16);
    acc.y += __shfl_xor_sync(0xffffffffu, acc.y, 16);
    acc.z += __shfl_xor_sync(0xffffffffu, acc.z, 16);
    acc.w += __shfl_xor_sync(0xffffffffu, acc.w, 16);
    sex   += __shfl_xor_sync(0xffffffffu, sex, 16);

    if (half == 0) {
        float inv = 1.0f / sex;
        float4 bv = *(const float4*)&bias[l * 4];
        float4 o;
        o.x = acc.x * inv + bv.x;
        o.y = acc.y * inv + bv.y;
        o.z = acc.z * inv + bv.z;
        o.w = acc.w * inv + bv.w;
        *(float4*)&g_o1[node * HC + l * 4] = o;
    }
}

// ---------------- GEMM2: h2 = relu(BN(o1)) @ W2, fused attention scalars ----------------
__global__ void k_gemm2(const float* __restrict__ W2,
                        const float* __restrict__ gamma, const float* __restrict__ beta,
                        const float* __restrict__ mean, const float* __restrict__ var,
                        const float* __restrict__ attS, const float* __restrict__ attD) {
    __shared__ __align__(16) float As[32][130];
    __shared__ __align__(16) float Bs[32][64];   // cols >= 40 zero
    __shared__ float sc[64], sh[64];
    int tid = threadIdx.x;
    if (tid < 64) {
        float s = gamma[tid] * rsqrtf(var[tid] + BNEPS);
        sc[tid] = s;
        sh[tid] = beta[tid] - mean[tid] * s;
    }
    __syncthreads();
    int tx = tid & 15, ty = tid >> 4;
    int mBase = blockIdx.x * 128;

    float as_v[4], ad_v[4];
#pragma unroll
    for (int j = 0; j < 4; j++) {
        int c = tx * 4 + j;
        int cc = (c < NC) ? c : NC - 1;
        as_v[j] = attS[cc];
        ad_v[j] = attD[cc];
    }

    ull acc[4][4];
#pragma unroll
    for (int p = 0; p < 4; p++)
#pragma unroll
        for (int j = 0; j < 4; j++) acc[p][j] = 0ull;

    for (int k0 = 0; k0 < HC; k0 += 32) {
        for (int idx = tid; idx < 128 * 32; idx += 256) {
            int m = idx >> 5, kk = idx & 31;
            int gm = mBase + m;
            int k = k0 + kk;
            float v = (gm < NN) ? g_o1[gm * HC + k] : 0.f;
            As[kk][m] = fmaxf(v * sc[k] + sh[k], 0.f);
        }
        for (int idx = tid; idx < 32 * 64; idx += 256) {
            int r = idx >> 6, c = idx & 63;
            Bs[r][c] = (c < NC) ? W2[(k0 + r) * NC + c] : 0.f;
        }
        __syncthreads();
#pragma unroll
        for (int kk = 0; kk < 32; kk++) {
            float4 bv = *(const float4*)&Bs[kk][tx * 4];
            ull b0 = splat2(bv.x), b1 = splat2(bv.y), b2 = splat2(bv.z), b3 = splat2(bv.w);
#pragma unroll
            for (int p = 0; p < 4; p++) {
                ull a = *(const ull*)&As[kk][ty * 8 + 2 * p];
                acc[p][0] = fma2(a, b0, acc[p][0]);
                acc[p][1] = fma2(a, b1, acc[p][1]);
                acc[p][2] = fma2(a, b2, acc[p][2]);
                acc[p][3] = fma2(a, b3, acc[p][3]);
            }
        }
        __syncthreads();
    }

#pragma unroll
    for (int p = 0; p < 4; p++) {
        float lo[4], hi[4];
#pragma unroll
        for (int j = 0; j < 4; j++) unpack2(acc[p][j], lo[j], hi[j]);
#pragma unroll
        for (int half = 0; half < 2; half++) {
            float* f = half ? hi : lo;
            int r = 2 * p + half;
            int gm = mBase + ty * 8 + r;
            float ps = 0.f, pd = 0.f;
            if (gm < NN) {
                if (tx < 10)
                    *(float4*)&g_h2[gm * NC + tx * 4] = make_float4(f[0], f[1], f[2], f[3]);
                ps = f[0] * as_v[0] + f[1] * as_v[1] + f[2] * as_v[2] + f[3] * as_v[3];
                pd = f[0] * ad_v[0] + f[1] * ad_v[1] + f[2] * ad_v[2] + f[3] * ad_v[3];
            }
#pragma unroll
            for (int o = 8; o >= 1; o >>= 1) {
                ps += __shfl_xor_sync(0xffffffffu, ps, o);
                pd += __shfl_xor_sync(0xffffffffu, pd, o);
            }
            if (gm < NN && tx == 0) {
                g_as2[gm] = ps;
                g_ad2[gm] = pd;
            }
        }
    }
}

// ---------------- layer-2 softmax aggregation: 3 edges/warp-iter ----------------
__global__ void k_agg2(const float* __restrict__ bias, float* __restrict__ out) {
    int t = blockIdx.x * blockDim.x + threadIdx.x;
    int node = t >> 5, lane = t & 31;
    if (node >= NN) return;
    int beg = g_rowptr[node], end = g_rowptr[node + 1];
    float ad = g_ad2[node];

    // pass 1: max (all 32 lanes stride edges)
    float m = -1e30f;
    for (int i = beg + lane; i < end; i += 32) {
        int s = g_srcs[i];
        float a = g_as2[s] + ad;
        a = fmaxf(a, SLOPE * a);
        m = fmaxf(m, a);
    }
#pragma unroll
    for (int o = 16; o >= 1; o >>= 1)
        m = fmaxf(m, __shfl_xor_sync(0xffffffffu, m, o));

    // pass 2: 10 lanes per edge (float4), 3 edges per iteration (lanes 30,31 idle)
    int grp = lane / 10;               // 0,1,2 active; 3 for lanes 30,31
    int l = lane - grp * 10;           // 0..9
    float4 acc = make_float4(0.f, 0.f, 0.f, 0.f);
    float sex = 0.f;
    if (grp < 3) {
        int i = beg + grp;
        int s = (i < end) ? g_srcs[i] : 0;
        while (i < end) {
            int inext = i + 3;
            int snext = (inext < end) ? g_srcs[inext] : 0;
            float a = g_as2[s] + ad;
            a = fmaxf(a, SLOPE * a);
            float ex = __expf(a - m);
            float4 hv = *(const float4*)&g_h2[s * NC + l * 4];
            acc.x += ex * hv.x; acc.y += ex * hv.y;
            acc.z += ex * hv.z; acc.w += ex * hv.w;
            sex += ex;
            i = inext; s = snext;
        }
    }
    // combine grp 0,1,2 (for lanes 0..9: read lanes l+10, l+20)
    int s1 = l + 10, s2 = l + 20;
    acc.x += __shfl_sync(0xffffffffu, acc.x, s1) + __shfl_sync(0xffffffffu, acc.x, s2);
    acc.y += __shfl_sync(0xffffffffu, acc.y, s1) + __shfl_sync(0xffffffffu, acc.y, s2);
    acc.z += __shfl_sync(0xffffffffu, acc.z, s1) + __shfl_sync(0xffffffffu, acc.z, s2);
    acc.w += __shfl_sync(0xffffffffu, acc.w, s1) + __shfl_sync(0xffffffffu, acc.w, s2);
    sex   += __shfl_sync(0xffffffffu, sex, s1) + __shfl_sync(0xffffffffu, sex, s2);

    if (grp == 0) {
        float inv = 1.0f / sex;
        float4 bv = *(const float4*)&bias[l * 4];
        float4 o;
        o.x = acc.x * inv + bv.x;
        o.y = acc.y * inv + bv.y;
        o.z = acc.z * inv + bv.z;
        o.w = acc.w * inv + bv.w;
        *(float4*)&out[node * NC + l * 4] = o;
    }
}

// ---------------- launch ----------------
extern "C" void kernel_launch(void* const* d_in, const int* in_sizes, int n_in,
                              void* d_out, int out_size) {
    const float* x    = (const float*)d_in[0];
    const void*  ei   = d_in[1];
    const float* W1   = (const float*)d_in[2];
    const float* as1  = (const float*)d_in[3];
    const float* ad1  = (const float*)d_in[4];
    const float* b1   = (const float*)d_in[5];
    const float* bngm = (const float*)d_in[6];
    const float* bnbt = (const float*)d_in[7];
    const float* bnmu = (const float*)d_in[8];
    const float* bnvr = (const float*)d_in[9];
    const float* W2   = (const float*)d_in[10];
    const float* as2  = (const float*)d_in[11];
    const float* ad2  = (const float*)d_in[12];
    const float* b2   = (const float*)d_in[13];
    float*       out  = (float*)d_out;

    k_init<<<(NN + 255) / 256, 256>>>(ei);
    k_convert_hist<<<(ET + 255) / 256, 256>>>(ei);
    int nb = (NN + 1023) / 1024;
    k_scan1<<<nb, 1024>>>();
    k_scan2<<<1, 32>>>(nb);
    k_scan3<<<(NN + 255) / 256, 256>>>();
    k_scatter<<<(ET + 255) / 256, 256>>>();

    k_gemm1<<<(NN + 127) / 128, 256>>>(x, W1, as1, ad1);
    k_agg1<<<(NN * 32 + 255) / 256, 256>>>(b1);

    k_gemm2<<<(NN + 127) / 128, 256>>>(W2, bngm, bnbt, bnmu, bnvr, as2, ad2);
    k_agg2<<<(NN * 32 + 255) / 256, 256>>>(b2, out);
}

// round 4
// speedup vs baseline: 1.3172x; 1.1415x over previous
#include <cuda_runtime.h>
#include <math.h>

#define NN 100000
#define EE 1600000
#define ET (EE + NN)
#define FEAT 128
#define HC 64
#define NH 4
#define NC 40
#define SLOPE 0.2f
#define BNEPS 1e-5f
#define NB ((NN + 1023) / 1024)

typedef unsigned long long ull;

// ---------------- scratch ----------------
__device__ float g_h1[NN * HC];
__device__ float g_o1[NN * HC];
__device__ float g_h2[NN * NC];
__device__ float g_as1[NN * NH];
__device__ float g_ad1[NN * NH];
__device__ float g_as2[NN];
__device__ float g_ad2[NN];
__device__ int   g_rowptr[NN + 1];
__device__ int   g_cursor[NN];
__device__ int   g_cnt[NN];
__device__ int   g_srcs[ET];
__device__ int   g_src[ET];
__device__ int   g_dst[ET];
__device__ int   g_bsum[128];
__device__ int   g_is64;

// ---------------- f32x2 helpers ----------------
__device__ __forceinline__ ull fma2(ull a, ull b, ull c) {
    ull d;
    asm("fma.rn.f32x2 %0, %1, %2, %3;" : "=l"(d) : "l"(a), "l"(b), "l"(c));
    return d;
}
__device__ __forceinline__ ull splat2(float x) {
    ull r;
    asm("mov.b64 %0, {%1, %1};" : "=l"(r) : "f"(x));
    return r;
}
__device__ __forceinline__ void unpack2(ull v, float& lo, float& hi) {
    asm("mov.b64 {%0, %1}, %2;" : "=f"(lo), "=f"(hi) : "l"(v));
}

// ---------------- init: zero counters + edge dtype probe ----------------
__global__ void k_init(const void* ei) {
    int i = blockIdx.x * blockDim.x + threadIdx.x;
    if (i < NN) g_cnt[i] = 0;
    if (i == 0) {
        const long long* p = (const long long*)ei;
        int is64 = 1;
        for (int j = 0; j < 8; j++) {
            long long v = p[j];
            if (v < 0 || v >= NN) { is64 = 0; break; }
        }
        g_is64 = is64;
    }
}

// ---------------- convert + histogram (fused) ----------------
__global__ void k_convert_hist(const void* ei) {
    int e = blockIdx.x * blockDim.x + threadIdx.x;
    if (e >= ET) return;
    int src, dst;
    if (e < EE) {
        if (g_is64) {
            const long long* p = (const long long*)ei;
            src = (int)p[e];
            dst = (int)p[EE + e];
        } else {
            const int* p = (const int*)ei;
            src = p[e];
            dst = p[EE + e];
        }
    } else {
        src = e - EE;
        dst = src;
    }
    g_src[e] = src;
    g_dst[e] = dst;
    atomicAdd(&g_cnt[dst], 1);
}

// ---------------- scan (2 kernels: per-block scan, then fused fixup) ----------------
__global__ void k_scan1() {  // blockDim = 1024
    int i = blockIdx.x * 1024 + threadIdx.x;
    int v = (i < NN) ? g_cnt[i] : 0;
    int x = v;
#pragma unroll
    for (int o = 1; o < 32; o <<= 1) {
        int y = __shfl_up_sync(0xffffffffu, x, o);
        if ((threadIdx.x & 31) >= o) x += y;
    }
    __shared__ int ws[32];
    if ((threadIdx.x & 31) == 31) ws[threadIdx.x >> 5] = x;
    __syncthreads();
    if (threadIdx.x < 32) {
        int w = ws[threadIdx.x];
#pragma unroll
        for (int o = 1; o < 32; o <<= 1) {
            int y = __shfl_up_sync(0xffffffffu, w, o);
            if (threadIdx.x >= o) w += y;
        }
        ws[threadIdx.x] = w;
    }
    __syncthreads();
    int add = (threadIdx.x >= 32) ? ws[(threadIdx.x >> 5) - 1] : 0;
    int incl = x + add;
    if (i < NN) g_rowptr[i] = incl - v;
    if (threadIdx.x == 1023) g_bsum[blockIdx.x] = incl;
}

// fixup: every block redundantly scans the 98 block sums in shared memory
__global__ void k_scan3() {
    __shared__ int sb[128];
    int tid = threadIdx.x;
    if (tid < 128) sb[tid] = (tid < NB) ? g_bsum[tid] : 0;
    __syncthreads();
#pragma unroll
    for (int o = 1; o < 128; o <<= 1) {
        int t = 0;
        if (tid < 128 && tid >= o) t = sb[tid - o];
        __syncthreads();
        if (tid < 128) sb[tid] += t;
        __syncthreads();
    }
    int i = blockIdx.x * blockDim.x + tid;
    if (i < NN) {
        int blk = i >> 10;
        int r = g_rowptr[i] + (blk ? sb[blk - 1] : 0);
        g_rowptr[i] = r;
        g_cursor[i] = r;
    }
    if (i == 0) g_rowptr[NN] = ET;
}

__global__ void k_scatter() {
    int e = blockIdx.x * blockDim.x + threadIdx.x;
    if (e >= ET) return;
    int pos = atomicAdd(&g_cursor[g_dst[e]], 1);
    g_srcs[pos] = g_src[e];
}

// ---------------- GEMM1: h1 = x @ W1, fused attention scalars (f32x2) ----------------
__global__ void k_gemm1(const float* __restrict__ x, const float* __restrict__ W,
                        const float* __restrict__ attS, const float* __restrict__ attD) {
    __shared__ __align__(16) float As[32][130];
    __shared__ __align__(16) float Bs[32][64];
    int tid = threadIdx.x;
    int tx = tid & 15, ty = tid >> 4;
    int mBase = blockIdx.x * 128;

    float as_v[4], ad_v[4];
#pragma unroll
    for (int j = 0; j < 4; j++) {
        as_v[j] = attS[tx * 4 + j];
        ad_v[j] = attD[tx * 4 + j];
    }

    ull acc[4][4];
#pragma unroll
    for (int p = 0; p < 4; p++)
#pragma unroll
        for (int j = 0; j < 4; j++) acc[p][j] = 0ull;

    for (int k0 = 0; k0 < FEAT; k0 += 32) {
        for (int idx = tid; idx < 128 * 32; idx += 256) {
            int m = idx >> 5, kk = idx & 31;
            int gm = mBase + m;
            As[kk][m] = (gm < NN) ? x[gm * FEAT + k0 + kk] : 0.f;
        }
        for (int idx = tid; idx < 32 * 64; idx += 256)
            Bs[idx >> 6][idx & 63] = W[(k0 + (idx >> 6)) * HC + (idx & 63)];
        __syncthreads();
#pragma unroll
        for (int kk = 0; kk < 32; kk++) {
            float4 bv = *(const float4*)&Bs[kk][tx * 4];
            ull b0 = splat2(bv.x), b1 = splat2(bv.y), b2 = splat2(bv.z), b3 = splat2(bv.w);
#pragma unroll
            for (int p = 0; p < 4; p++) {
                ull a = *(const ull*)&As[kk][ty * 8 + 2 * p];
                acc[p][0] = fma2(a, b0, acc[p][0]);
                acc[p][1] = fma2(a, b1, acc[p][1]);
                acc[p][2] = fma2(a, b2, acc[p][2]);
                acc[p][3] = fma2(a, b3, acc[p][3]);
            }
        }
        __syncthreads();
    }

#pragma unroll
    for (int p = 0; p < 4; p++) {
        float lo[4], hi[4];
#pragma unroll
        for (int j = 0; j < 4; j++) unpack2(acc[p][j], lo[j], hi[j]);
#pragma unroll
        for (int half = 0; half < 2; half++) {
            float* f = half ? hi : lo;
            int r = 2 * p + half;
            int gm = mBase + ty * 8 + r;
            if (gm < NN) {
                *(float4*)&g_h1[gm * HC + tx * 4] = make_float4(f[0], f[1], f[2], f[3]);
                float ps = f[0] * as_v[0] + f[1] * as_v[1] + f[2] * as_v[2] + f[3] * as_v[3];
                float pd = f[0] * ad_v[0] + f[1] * ad_v[1] + f[2] * ad_v[2] + f[3] * ad_v[3];
                ps += __shfl_xor_sync(0xffffffffu, ps, 1);
                pd += __shfl_xor_sync(0xffffffffu, pd, 1);
                ps += __shfl_xor_sync(0xffffffffu, ps, 2);
                pd += __shfl_xor_sync(0xffffffffu, pd, 2);
                if ((tx & 3) == 0) {
                    g_as1[gm * NH + (tx >> 2)] = ps;
                    g_ad1[gm * NH + (tx >> 2)] = pd;
                }
            } else {
                float z = 0.f;
                z += __shfl_xor_sync(0xffffffffu, z, 1);
                z += __shfl_xor_sync(0xffffffffu, z, 1);
                z += __shfl_xor_sync(0xffffffffu, z, 2);
                z += __shfl_xor_sync(0xffffffffu, z, 2);
            }
        }
    }
}

// ---------------- layer-1 softmax aggregation: single fused pass (no max) ----------------
__global__ void k_agg1(const float* __restrict__ bias) {
    int t = blockIdx.x * blockDim.x + threadIdx.x;
    int node = t >> 5, lane = t & 31;
    if (node >= NN) return;
    int beg = g_rowptr[node], end = g_rowptr[node + 1];
    float4 adv = *(const float4*)&g_ad1[node * NH];

    // 16 lanes per edge (float4 channels), 2 edges per iteration
    int half = lane >> 4;
    int l = lane & 15;           // channel group: channels l*4 .. l*4+3
    int hsel = l >> 2;           // head
    float adh = (hsel == 0) ? adv.x : (hsel == 1) ? adv.y : (hsel == 2) ? adv.z : adv.w;

    float4 acc = make_float4(0.f, 0.f, 0.f, 0.f);
    float sex = 0.f;
    int i = beg + half;
    int s = (i < end) ? g_srcs[i] : 0;
    while (i < end) {
        int inext = i + 2;
        int snext = (inext < end) ? g_srcs[inext] : 0;
        float a = g_as1[s * NH + hsel] + adh;
        a = fmaxf(a, SLOPE * a);
        float ex = __expf(a);
        float4 hv = *(const float4*)&g_h1[s * HC + l * 4];
        acc.x += ex * hv.x; acc.y += ex * hv.y;
        acc.z += ex * hv.z; acc.w += ex * hv.w;
        sex += ex;
        i = inext; s = snext;
    }
    acc.x += __shfl_xor_sync(0xffffffffu, acc.x, 16);
    acc.y += __shfl_xor_sync(0xffffffffu, acc.y, 16);
    acc.z += __shfl_xor_sync(0xffffffffu, acc.z, 16);
    acc.w += __shfl_xor_sync(0xffffffffu, acc.w, 16);
    sex   += __shfl_xor_sync(0xffffffffu, sex, 16);

    if (half == 0) {
        float inv = 1.0f / sex;
        float4 bv = *(const float4*)&bias[l * 4];
        float4 o;
        o.x = acc.x * inv + bv.x;
        o.y = acc.y * inv + bv.y;
        o.z = acc.z * inv + bv.z;
        o.w = acc.w * inv + bv.w;
        *(float4*)&g_o1[node * HC + l * 4] = o;
    }
}

// ---------------- GEMM2: h2 = relu(BN(o1)) @ W2, fused attention scalars ----------------
__global__ void k_gemm2(const float* __restrict__ W2,
                        const float* __restrict__ gamma, const float* __restrict__ beta,
                        const float* __restrict__ mean, const float* __restrict__ var,
                        const float* __restrict__ attS, const float* __restrict__ attD) {
    __shared__ __align__(16) float As[32][130];
    __shared__ __align__(16) float Bs[32][64];
    __shared__ float sc[64], sh[64];
    int tid = threadIdx.x;
    if (tid < 64) {
        float s = gamma[tid] * rsqrtf(var[tid] + BNEPS);
        sc[tid] = s;
        sh[tid] = beta[tid] - mean[tid] * s;
    }
    __syncthreads();
    int tx = tid & 15, ty = tid >> 4;
    int mBase = blockIdx.x * 128;

    float as_v[4], ad_v[4];
#pragma unroll
    for (int j = 0; j < 4; j++) {
        int c = tx * 4 + j;
        int cc = (c < NC) ? c : NC - 1;
        as_v[j] = attS[cc];
        ad_v[j] = attD[cc];
    }

    ull acc[4][4];
#pragma unroll
    for (int p = 0; p < 4; p++)
#pragma unroll
        for (int j = 0; j < 4; j++) acc[p][j] = 0ull;

    for (int k0 = 0; k0 < HC; k0 += 32) {
        for (int idx = tid; idx < 128 * 32; idx += 256) {
            int m = idx >> 5, kk = idx & 31;
            int gm = mBase + m;
            int k = k0 + kk;
            float v = (gm < NN) ? g_o1[gm * HC + k] : 0.f;
            As[kk][m] = fmaxf(v * sc[k] + sh[k], 0.f);
        }
        for (int idx = tid; idx < 32 * 64; idx += 256) {
            int r = idx >> 6, c = idx & 63;
            Bs[r][c] = (c < NC) ? W2[(k0 + r) * NC + c] : 0.f;
        }
        __syncthreads();
#pragma unroll
        for (int kk = 0; kk < 32; kk++) {
            float4 bv = *(const float4*)&Bs[kk][tx * 4];
            ull b0 = splat2(bv.x), b1 = splat2(bv.y), b2 = splat2(bv.z), b3 = splat2(bv.w);
#pragma unroll
            for (int p = 0; p < 4; p++) {
                ull a = *(const ull*)&As[kk][ty * 8 + 2 * p];
                acc[p][0] = fma2(a, b0, acc[p][0]);
                acc[p][1] = fma2(a, b1, acc[p][1]);
                acc[p][2] = fma2(a, b2, acc[p][2]);
                acc[p][3] = fma2(a, b3, acc[p][3]);
            }
        }
        __syncthreads();
    }

#pragma unroll
    for (int p = 0; p < 4; p++) {
        float lo[4], hi[4];
#pragma unroll
        for (int j = 0; j < 4; j++) unpack2(acc[p][j], lo[j], hi[j]);
#pragma unroll
        for (int half = 0; half < 2; half++) {
            float* f = half ? hi : lo;
            int r = 2 * p + half;
            int gm = mBase + ty * 8 + r;
            float ps = 0.f, pd = 0.f;
            if (gm < NN) {
                if (tx < 10)
                    *(float4*)&g_h2[gm * NC + tx * 4] = make_float4(f[0], f[1], f[2], f[3]);
                ps = f[0] * as_v[0] + f[1] * as_v[1] + f[2] * as_v[2] + f[3] * as_v[3];
                pd = f[0] * ad_v[0] + f[1] * ad_v[1] + f[2] * ad_v[2] + f[3] * ad_v[3];
            }
#pragma unroll
            for (int o = 8; o >= 1; o >>= 1) {
                ps += __shfl_xor_sync(0xffffffffu, ps, o);
                pd += __shfl_xor_sync(0xffffffffu, pd, o);
            }
            if (gm < NN && tx == 0) {
                g_as2[gm] = ps;
                g_ad2[gm] = pd;
            }
        }
    }
}

// ---------------- layer-2 softmax aggregation: single fused pass (no max) ----------------
__global__ void k_agg2(const float* __restrict__ bias, float* __restrict__ out) {
    int t = blockIdx.x * blockDim.x + threadIdx.x;
    int node = t >> 5, lane = t & 31;
    if (node >= NN) return;
    int beg = g_rowptr[node], end = g_rowptr[node + 1];
    float ad = g_ad2[node];

    // 10 lanes per edge (float4), 3 edges per iteration (lanes 30,31 idle)
    int grp = lane / 10;
    int l = lane - grp * 10;
    float4 acc = make_float4(0.f, 0.f, 0.f, 0.f);
    float sex = 0.f;
    if (grp < 3) {
        int i = beg + grp;
        int s = (i < end) ? g_srcs[i] : 0;
        while (i < end) {
            int inext = i + 3;
            int snext = (inext < end) ? g_srcs[inext] : 0;
            float a = g_as2[s] + ad;
            a = fmaxf(a, SLOPE * a);
            float ex = __expf(a);
            float4 hv = *(const float4*)&g_h2[s * NC + l * 4];
            acc.x += ex * hv.x; acc.y += ex * hv.y;
            acc.z += ex * hv.z; acc.w += ex * hv.w;
            sex += ex;
            i = inext; s = snext;
        }
    }
    int s1 = l + 10, s2 = l + 20;
    acc.x += __shfl_sync(0xffffffffu, acc.x, s1) + __shfl_sync(0xffffffffu, acc.x, s2);
    acc.y += __shfl_sync(0xffffffffu, acc.y, s1) + __shfl_sync(0xffffffffu, acc.y, s2);
    acc.z += __shfl_sync(0xffffffffu, acc.z, s1) + __shfl_sync(0xffffffffu, acc.z, s2);
    acc.w += __shfl_sync(0xffffffffu, acc.w, s1) + __shfl_sync(0xffffffffu, acc.w, s2);
    sex   += __shfl_sync(0xffffffffu, sex, s1) + __shfl_sync(0xffffffffu, sex, s2);

    if (grp == 0) {
        float inv = 1.0f / sex;
        float4 bv = *(const float4*)&bias[l * 4];
        float4 o;
        o.x = acc.x * inv + bv.x;
        o.y = acc.y * inv + bv.y;
        o.z = acc.z * inv + bv.z;
        o.w = acc.w * inv + bv.w;
        *(float4*)&out[node * NC + l * 4] = o;
    }
}

// ---------------- launch ----------------
extern "C" void kernel_launch(void* const* d_in, const int* in_sizes, int n_in,
                              void* d_out, int out_size) {
    const float* x    = (const float*)d_in[0];
    const void*  ei   = d_in[1];
    const float* W1   = (const float*)d_in[2];
    const float* as1  = (const float*)d_in[3];
    const float* ad1  = (const float*)d_in[4];
    const float* b1   = (const float*)d_in[5];
    const float* bngm = (const float*)d_in[6];
    const float* bnbt = (const float*)d_in[7];
    const float* bnmu = (const float*)d_in[8];
    const float* bnvr = (const float*)d_in[9];
    const float* W2   = (const float*)d_in[10];
    const float* as2  = (const float*)d_in[11];
    const float* ad2  = (const float*)d_in[12];
    const float* b2   = (const float*)d_in[13];
    float*       out  = (float*)d_out;

    k_init<<<(NN + 255) / 256, 256>>>(ei);
    k_convert_hist<<<(ET + 255) / 256, 256>>>(ei);
    k_scan1<<<NB, 1024>>>();
    k_scan3<<<(NN + 255) / 256, 256>>>();
    k_scatter<<<(ET + 255) / 256, 256>>>();

    k_gemm1<<<(NN + 127) / 128, 256>>>(x, W1, as1, ad1);
    k_agg1<<<(NN * 32 + 255) / 256, 256>>>(b1);

    k_gemm2<<<(NN + 127) / 128, 256>>>(W2, bngm, bnbt, bnmu, bnvr, as2, ad2);
    k_agg2<<<(NN * 32 + 255) / 256, 256>>>(b2, out);
}

// round 5
// speedup vs baseline: 1.4346x; 1.0892x over previous
#include <cuda_runtime.h>
#include <cuda_fp16.h>
#include <math.h>

#define NN 100000
#define EE 1600000
#define ET (EE + NN)
#define FEAT 128
#define HC 64
#define NH 4
#define NC 40
#define SLOPE 0.2f
#define BNEPS 1e-5f
#define NB ((NN + 1023) / 1024)

typedef unsigned long long ull;

// ---------------- scratch ----------------
__device__ __half g_h1[NN * HC];    // layer-1 features, fp16 (gathered in agg1)
__device__ float  g_o1[NN * HC];    // layer-1 GAT output, fp32 (feeds gemm2)
__device__ __half g_h2[NN * NC];    // layer-2 features, fp16 (gathered in agg2)
__device__ float  g_as1[NN * NH];
__device__ float  g_ad1[NN * NH];
__device__ float  g_as2[NN];
__device__ float  g_ad2[NN];
__device__ int    g_rowptr[NN + 1];
__device__ int    g_cursor[NN];
__device__ int    g_cnt[NN];        // zero-initialized; every launch restores to zero
__device__ int    g_srcs[ET];
__device__ int    g_src[ET];
__device__ int    g_dst[ET];
__device__ int    g_bsum[128];

// ---------------- f32x2 helpers ----------------
__device__ __forceinline__ ull fma2(ull a, ull b, ull c) {
    ull d;
    asm("fma.rn.f32x2 %0, %1, %2, %3;" : "=l"(d) : "l"(a), "l"(b), "l"(c));
    return d;
}
__device__ __forceinline__ ull splat2(float x) {
    ull r;
    asm("mov.b64 %0, {%1, %1};" : "=l"(r) : "f"(x));
    return r;
}
__device__ __forceinline__ void unpack2(ull v, float& lo, float& hi) {
    asm("mov.b64 {%0, %1}, %2;" : "=f"(lo), "=f"(hi) : "l"(v));
}

union HalfPack {
    __half2 h[2];
    uint2 u;
};

// ---------------- convert + histogram (fused, with per-block dtype probe) ----------------
__global__ void k_convert_hist(const void* ei) {
    __shared__ int sh_is64;
    if (threadIdx.x == 0) {
        const long long* p = (const long long*)ei;
        int is64 = 1;
        for (int j = 0; j < 8; j++) {
            long long v = p[j];
            if (v < 0 || v >= NN) { is64 = 0; break; }
        }
        sh_is64 = is64;
    }
    __syncthreads();
    int e = blockIdx.x * blockDim.x + threadIdx.x;
    if (e >= ET) return;
    int src, dst;
    if (e < EE) {
        if (sh_is64) {
            const long long* p = (const long long*)ei;
            src = (int)p[e];
            dst = (int)p[EE + e];
        } else {
            const int* p = (const int*)ei;
            src = p[e];
            dst = p[EE + e];
        }
    } else {
        src = e - EE;
        dst = src;
    }
    g_src[e] = src;
    g_dst[e] = dst;
    atomicAdd(&g_cnt[dst], 1);
}

// ---------------- scan: per-block scan (restores g_cnt to zero), then fused fixup ----------------
__global__ void k_scan1() {  // blockDim = 1024
    int i = blockIdx.x * 1024 + threadIdx.x;
    int v = 0;
    if (i < NN) {
        v = g_cnt[i];
        g_cnt[i] = 0;           // restore invariant for next launch
    }
    int x = v;
#pragma unroll
    for (int o = 1; o < 32; o <<= 1) {
        int y = __shfl_up_sync(0xffffffffu, x, o);
        if ((threadIdx.x & 31) >= o) x += y;
    }
    __shared__ int ws[32];
    if ((threadIdx.x & 31) == 31) ws[threadIdx.x >> 5] = x;
    __syncthreads();
    if (threadIdx.x < 32) {
        int w = ws[threadIdx.x];
#pragma unroll
        for (int o = 1; o < 32; o <<= 1) {
            int y = __shfl_up_sync(0xffffffffu, w, o);
            if (threadIdx.x >= o) w += y;
        }
        ws[threadIdx.x] = w;
    }
    __syncthreads();
    int add = (threadIdx.x >= 32) ? ws[(threadIdx.x >> 5) - 1] : 0;
    int incl = x + add;
    if (i < NN) g_rowptr[i] = incl - v;
    if (threadIdx.x == 1023) g_bsum[blockIdx.x] = incl;
}

__global__ void k_scan3() {
    __shared__ int sb[128];
    int tid = threadIdx.x;
    if (tid < 128) sb[tid] = (tid < NB) ? g_bsum[tid] : 0;
    __syncthreads();
#pragma unroll
    for (int o = 1; o < 128; o <<= 1) {
        int t = 0;
        if (tid < 128 && tid >= o) t = sb[tid - o];
        __syncthreads();
        if (tid < 128) sb[tid] += t;
        __syncthreads();
    }
    int i = blockIdx.x * blockDim.x + tid;
    if (i < NN) {
        int blk = i >> 10;
        int r = g_rowptr[i] + (blk ? sb[blk - 1] : 0);
        g_rowptr[i] = r;
        g_cursor[i] = r;
    }
    if (i == 0) g_rowptr[NN] = ET;
}

__global__ void k_scatter() {
    int e = blockIdx.x * blockDim.x + threadIdx.x;
    if (e >= ET) return;
    int pos = atomicAdd(&g_cursor[g_dst[e]], 1);
    g_srcs[pos] = g_src[e];
}

// ---------------- GEMM1: h1 = x @ W1, fused attention scalars (f32x2), fp16 h1 store ----------------
__global__ void k_gemm1(const float* __restrict__ x, const float* __restrict__ W,
                        const float* __restrict__ attS, const float* __restrict__ attD) {
    __shared__ __align__(16) float As[32][130];
    __shared__ __align__(16) float Bs[32][64];
    int tid = threadIdx.x;
    int tx = tid & 15, ty = tid >> 4;
    int mBase = blockIdx.x * 128;

    float as_v[4], ad_v[4];
#pragma unroll
    for (int j = 0; j < 4; j++) {
        as_v[j] = attS[tx * 4 + j];
        ad_v[j] = attD[tx * 4 + j];
    }

    ull acc[4][4];
#pragma unroll
    for (int p = 0; p < 4; p++)
#pragma unroll
        for (int j = 0; j < 4; j++) acc[p][j] = 0ull;

    for (int k0 = 0; k0 < FEAT; k0 += 32) {
        for (int idx = tid; idx < 128 * 32; idx += 256) {
            int m = idx >> 5, kk = idx & 31;
            int gm = mBase + m;
            As[kk][m] = (gm < NN) ? x[gm * FEAT + k0 + kk] : 0.f;
        }
        for (int idx = tid; idx < 32 * 64; idx += 256)
            Bs[idx >> 6][idx & 63] = W[(k0 + (idx >> 6)) * HC + (idx & 63)];
        __syncthreads();
#pragma unroll
        for (int kk = 0; kk < 32; kk++) {
            float4 bv = *(const float4*)&Bs[kk][tx * 4];
            ull b0 = splat2(bv.x), b1 = splat2(bv.y), b2 = splat2(bv.z), b3 = splat2(bv.w);
#pragma unroll
            for (int p = 0; p < 4; p++) {
                ull a = *(const ull*)&As[kk][ty * 8 + 2 * p];
                acc[p][0] = fma2(a, b0, acc[p][0]);
                acc[p][1] = fma2(a, b1, acc[p][1]);
                acc[p][2] = fma2(a, b2, acc[p][2]);
                acc[p][3] = fma2(a, b3, acc[p][3]);
            }
        }
        __syncthreads();
    }

#pragma unroll
    for (int p = 0; p < 4; p++) {
        float lo[4], hi[4];
#pragma unroll
        for (int j = 0; j < 4; j++) unpack2(acc[p][j], lo[j], hi[j]);
#pragma unroll
        for (int half = 0; half < 2; half++) {
            float* f = half ? hi : lo;
            int r = 2 * p + half;
            int gm = mBase + ty * 8 + r;
            if (gm < NN) {
                HalfPack hp;
                hp.h[0] = __floats2half2_rn(f[0], f[1]);
                hp.h[1] = __floats2half2_rn(f[2], f[3]);
                *(uint2*)&g_h1[gm * HC + tx * 4] = hp.u;
                float ps = f[0] * as_v[0] + f[1] * as_v[1] + f[2] * as_v[2] + f[3] * as_v[3];
                float pd = f[0] * ad_v[0] + f[1] * ad_v[1] + f[2] * ad_v[2] + f[3] * ad_v[3];
                ps += __shfl_xor_sync(0xffffffffu, ps, 1);
                pd += __shfl_xor_sync(0xffffffffu, pd, 1);
                ps += __shfl_xor_sync(0xffffffffu, ps, 2);
                pd += __shfl_xor_sync(0xffffffffu, pd, 2);
                if ((tx & 3) == 0) {
                    g_as1[gm * NH + (tx >> 2)] = ps;
                    g_ad1[gm * NH + (tx >> 2)] = pd;
                }
            } else {
                float z = 0.f;
                z += __shfl_xor_sync(0xffffffffu, z, 1);
                z += __shfl_xor_sync(0xffffffffu, z, 1);
                z += __shfl_xor_sync(0xffffffffu, z, 2);
                z += __shfl_xor_sync(0xffffffffu, z, 2);
            }
        }
    }
}

// ---------------- layer-1 aggregation: fused pass, fp16 gathers ----------------
__global__ void k_agg1(const float* __restrict__ bias) {
    int t = blockIdx.x * blockDim.x + threadIdx.x;
    int node = t >> 5, lane = t & 31;
    if (node >= NN) return;
    int beg = g_rowptr[node], end = g_rowptr[node + 1];
    float4 adv = *(const float4*)&g_ad1[node * NH];

    int half = lane >> 4;        // which edge of the pair
    int l = lane & 15;           // channel group: channels l*4 .. l*4+3
    int hsel = l >> 2;           // head
    float adh = (hsel == 0) ? adv.x : (hsel == 1) ? adv.y : (hsel == 2) ? adv.z : adv.w;

    float4 acc = make_float4(0.f, 0.f, 0.f, 0.f);
    float sex = 0.f;
    int i = beg + half;
    int s = (i < end) ? g_srcs[i] : 0;
    while (i < end) {
        int inext = i + 2;
        int snext = (inext < end) ? g_srcs[inext] : 0;
        float a = g_as1[s * NH + hsel] + adh;
        a = fmaxf(a, SLOPE * a);
        float ex = __expf(a);
        HalfPack hp;
        hp.u = *(const uint2*)&g_h1[s * HC + l * 4];
        float2 f01 = __half22float2(hp.h[0]);
        float2 f23 = __half22float2(hp.h[1]);
        acc.x += ex * f01.x; acc.y += ex * f01.y;
        acc.z += ex * f23.x; acc.w += ex * f23.y;
        sex += ex;
        i = inext; s = snext;
    }
    acc.x += __shfl_xor_sync(0xffffffffu, acc.x, 16);
    acc.y += __shfl_xor_sync(0xffffffffu, acc.y, 16);
    acc.z += __shfl_xor_sync(0xffffffffu, acc.z, 16);
    acc.w += __shfl_xor_sync(0xffffffffu, acc.w, 16);
    sex   += __shfl_xor_sync(0xffffffffu, sex, 16);

    if (half == 0) {
        float inv = 1.0f / sex;
        float4 bv = *(const float4*)&bias[l * 4];
        float4 o;
        o.x = acc.x * inv + bv.x;
        o.y = acc.y * inv + bv.y;
        o.z = acc.z * inv + bv.z;
        o.w = acc.w * inv + bv.w;
        *(float4*)&g_o1[node * HC + l * 4] = o;
    }
}

// ---------------- GEMM2: h2 = relu(BN(o1)) @ W2, fused attn scalars, fp16 h2 store ----------------
__global__ void k_gemm2(const float* __restrict__ W2,
                        const float* __restrict__ gamma, const float* __restrict__ beta,
                        const float* __restrict__ mean, const float* __restrict__ var,
                        const float* __restrict__ attS, const float* __restrict__ attD) {
    __shared__ __align__(16) float As[32][130];
    __shared__ __align__(16) float Bs[32][64];
    __shared__ float sc[64], sh[64];
    int tid = threadIdx.x;
    if (tid < 64) {
        float s = gamma[tid] * rsqrtf(var[tid] + BNEPS);
        sc[tid] = s;
        sh[tid] = beta[tid] - mean[tid] * s;
    }
    __syncthreads();
    int tx = tid & 15, ty = tid >> 4;
    int mBase = blockIdx.x * 128;

    float as_v[4], ad_v[4];
#pragma unroll
    for (int j = 0; j < 4; j++) {
        int c = tx * 4 + j;
        int cc = (c < NC) ? c : NC - 1;
        as_v[j] = attS[cc];
        ad_v[j] = attD[cc];
    }

    ull acc[4][4];
#pragma unroll
    for (int p = 0; p < 4; p++)
#pragma unroll
        for (int j = 0; j < 4; j++) acc[p][j] = 0ull;

    for (int k0 = 0; k0 < HC; k0 += 32) {
        for (int idx = tid; idx < 128 * 32; idx += 256) {
            int m = idx >> 5, kk = idx & 31;
            int gm = mBase + m;
            int k = k0 + kk;
            float v = (gm < NN) ? g_o1[gm * HC + k] : 0.f;
            As[kk][m] = fmaxf(v * sc[k] + sh[k], 0.f);
        }
        for (int idx = tid; idx < 32 * 64; idx += 256) {
            int r = idx >> 6, c = idx & 63;
            Bs[r][c] = (c < NC) ? W2[(k0 + r) * NC + c] : 0.f;
        }
        __syncthreads();
#pragma unroll
        for (int kk = 0; kk < 32; kk++) {
            float4 bv = *(const float4*)&Bs[kk][tx * 4];
            ull b0 = splat2(bv.x), b1 = splat2(bv.y), b2 = splat2(bv.z), b3 = splat2(bv.w);
#pragma unroll
            for (int p = 0; p < 4; p++) {
                ull a = *(const ull*)&As[kk][ty * 8 + 2 * p];
                acc[p][0] = fma2(a, b0, acc[p][0]);
                acc[p][1] = fma2(a, b1, acc[p][1]);
                acc[p][2] = fma2(a, b2, acc[p][2]);
                acc[p][3] = fma2(a, b3, acc[p][3]);
            }
        }
        __syncthreads();
    }

#pragma unroll
    for (int p = 0; p < 4; p++) {
        float lo[4], hi[4];
#pragma unroll
        for (int j = 0; j < 4; j++) unpack2(acc[p][j], lo[j], hi[j]);
#pragma unroll
        for (int half = 0; half < 2; half++) {
            float* f = half ? hi : lo;
            int r = 2 * p + half;
            int gm = mBase + ty * 8 + r;
            float ps = 0.f, pd = 0.f;
            if (gm < NN) {
                if (tx < 10) {
                    HalfPack hp;
                    hp.h[0] = __floats2half2_rn(f[0], f[1]);
                    hp.h[1] = __floats2half2_rn(f[2], f[3]);
                    *(uint2*)&g_h2[gm * NC + tx * 4] = hp.u;
                }
                ps = f[0] * as_v[0] + f[1] * as_v[1] + f[2] * as_v[2] + f[3] * as_v[3];
                pd = f[0] * ad_v[0] + f[1] * ad_v[1] + f[2] * ad_v[2] + f[3] * ad_v[3];
            }
#pragma unroll
            for (int o = 8; o >= 1; o >>= 1) {
                ps += __shfl_xor_sync(0xffffffffu, ps, o);
                pd += __shfl_xor_sync(0xffffffffu, pd, o);
            }
            if (gm < NN && tx == 0) {
                g_as2[gm] = ps;
                g_ad2[gm] = pd;
            }
        }
    }
}

// ---------------- layer-2 aggregation: fused pass, fp16 gathers ----------------
__global__ void k_agg2(const float* __restrict__ bias, float* __restrict__ out) {
    int t = blockIdx.x * blockDim.x + threadIdx.x;
    int node = t >> 5, lane = t & 31;
    if (node >= NN) return;
    int beg = g_rowptr[node], end = g_rowptr[node + 1];
    float ad = g_ad2[node];

    int grp = lane / 10;               // 0,1,2 active; lanes 30,31 idle
    int l = lane - grp * 10;           // 0..9
    float4 acc = make_float4(0.f, 0.f, 0.f, 0.f);
    float sex = 0.f;
    if (grp < 3) {
        int i = beg + grp;
        int s = (i < end) ? g_srcs[i] : 0;
        while (i < end) {
            int inext = i + 3;
            int snext = (inext < end) ? g_srcs[inext] : 0;
            float a = g_as2[s] + ad;
            a = fmaxf(a, SLOPE * a);
            float ex = __expf(a);
            HalfPack hp;
            hp.u = *(const uint2*)&g_h2[s * NC + l * 4];
            float2 f01 = __half22float2(hp.h[0]);
            float2 f23 = __half22float2(hp.h[1]);
            acc.x += ex * f01.x; acc.y += ex * f01.y;
            acc.z += ex * f23.x; acc.w += ex * f23.y;
            sex += ex;
            i = inext; s = snext;
        }
    }
    int s1 = l + 10, s2 = l + 20;
    acc.x += __shfl_sync(0xffffffffu, acc.x, s1) + __shfl_sync(0xffffffffu, acc.x, s2);
    acc.y += __shfl_sync(0xffffffffu, acc.y, s1) + __shfl_sync(0xffffffffu, acc.y, s2);
    acc.z += __shfl_sync(0xffffffffu, acc.z, s1) + __shfl_sync(0xffffffffu, acc.z, s2);
    acc.w += __shfl_sync(0xffffffffu, acc.w, s1) + __shfl_sync(0xffffffffu, acc.w, s2);
    sex   += __shfl_sync(0xffffffffu, sex, s1) + __shfl_sync(0xffffffffu, sex, s2);

    if (grp == 0) {
        float inv = 1.0f / sex;
        float4 bv = *(const float4*)&bias[l * 4];
        float4 o;
        o.x = acc.x * inv + bv.x;
        o.y = acc.y * inv + bv.y;
        o.z = acc.z * inv + bv.z;
        o.w = acc.w * inv + bv.w;
        *(float4*)&out[node * NC + l * 4] = o;
    }
}

// ---------------- launch (fork-join: CSR build overlaps GEMM1) ----------------
extern "C" void kernel_launch(void* const* d_in, const int* in_sizes, int n_in,
                              void* d_out, int out_size) {
    const float* x    = (const float*)d_in[0];
    const void*  ei   = d_in[1];
    const float* W1   = (const float*)d_in[2];
    const float* as1  = (const float*)d_in[3];
    const float* ad1  = (const float*)d_in[4];
    const float* b1   = (const float*)d_in[5];
    const float* bngm = (const float*)d_in[6];
    const float* bnbt = (const float*)d_in[7];
    const float* bnmu = (const float*)d_in[8];
    const float* bnvr = (const float*)d_in[9];
    const float* W2   = (const float*)d_in[10];
    const float* as2  = (const float*)d_in[11];
    const float* ad2  = (const float*)d_in[12];
    const float* b2   = (const float*)d_in[13];
    float*       out  = (float*)d_out;

    static cudaStream_t s2 = nullptr;
    static cudaEvent_t evA = nullptr, evB = nullptr;
    if (s2 == nullptr) {
        cudaStreamCreateWithFlags(&s2, cudaStreamNonBlocking);
        cudaEventCreateWithFlags(&evA, cudaEventDisableTiming);
        cudaEventCreateWithFlags(&evB, cudaEventDisableTiming);
    }

    // fork: CSR chain on s2, GEMM1 on the main stream
    cudaEventRecord(evA, 0);
    cudaStreamWaitEvent(s2, evA, 0);

    k_convert_hist<<<(ET + 255) / 256, 256, 0, s2>>>(ei);
    k_scan1<<<NB, 1024, 0, s2>>>();
    k_scan3<<<(NN + 255) / 256, 256, 0, s2>>>();
    k_scatter<<<(ET + 255) / 256, 256, 0, s2>>>();
    cudaEventRecord(evB, s2);

    k_gemm1<<<(NN + 127) / 128, 256>>>(x, W1, as1, ad1);

    // join
    cudaStreamWaitEvent(0, evB, 0);

    k_agg1<<<(NN * 32 + 255) / 256, 256>>>(b1);
    k_gemm2<<<(NN + 127) / 128, 256>>>(W2, bngm, bnbt, bnmu, bnvr, as2, ad2);
    k_agg2<<<(NN * 32 + 255) / 256, 256>>>(b2, out);
}